// round 12
// baseline (speedup 1.0000x reference)
#include <cuda_runtime.h>
#include <cuda_bf16.h>
#include <cuda_fp16.h>
#include <cstdint>

#define BATCH 256
#define NA 196
#define NB 196
#define DK 256
#define DIM 1024
#define SMOOTH_F 4.0f
#define NP 224   // padded n / a dims

// Attention weights, transposed [b][n][a], single fp16 plane, zero-padded.
__device__ unsigned short g_ah[(size_t)BATCH * NP * NP];

typedef unsigned int u32;

__device__ __forceinline__ u32 smem_u32(const void* p) {
    u32 a;
    asm("{ .reg .u64 t; cvta.to.shared.u64 t, %1; cvt.u32.u64 %0, t; }" : "=r"(a) : "l"(p));
    return a;
}
// bf16 2-term split (k1 energy GEMM — softmax-sensitive, keep high precision)
__device__ __forceinline__ void split2(float x, unsigned short& h, unsigned short& l) {
    __nv_bfloat16 hb = __float2bfloat16_rn(x);
    float r = x - __bfloat162float(hb);
    h = __bfloat16_as_ushort(hb);
    l = __bfloat16_as_ushort(__float2bfloat16_rn(r));
}
// fp16 2-term split (k2 V_a — exact to ~2^-22)
__device__ __forceinline__ void split2h(float x, unsigned short& h, unsigned short& l) {
    __half hb = __float2half_rn(x);
    float r = x - __half2float(hb);
    h = __half_as_ushort(hb);
    l = __half_as_ushort(__float2half_rn(r));
}

#define LDMX4(r, a) asm volatile( \
    "ldmatrix.sync.aligned.m8n8.x4.shared.b16 {%0,%1,%2,%3}, [%4];" \
    : "=r"((r)[0]), "=r"((r)[1]), "=r"((r)[2]), "=r"((r)[3]) : "r"(a))

#define MMA16816(d, a, b0, b1) asm volatile( \
    "mma.sync.aligned.m16n8k16.row.col.f32.bf16.bf16.f32 " \
    "{%0,%1,%2,%3}, {%4,%5,%6,%7}, {%8,%9}, {%0,%1,%2,%3};" \
    : "+f"((d)[0]), "+f"((d)[1]), "+f"((d)[2]), "+f"((d)[3]) \
    : "r"((a)[0]), "r"((a)[1]), "r"((a)[2]), "r"((a)[3]), "r"(b0), "r"(b1))

#define MMAF16816(d, a, b0, b1) asm volatile( \
    "mma.sync.aligned.m16n8k16.row.col.f32.f16.f16.f32 " \
    "{%0,%1,%2,%3}, {%4,%5,%6,%7}, {%8,%9}, {%0,%1,%2,%3};" \
    : "+f"((d)[0]), "+f"((d)[1]), "+f"((d)[2]), "+f"((d)[3]) \
    : "r"((a)[0]), "r"((a)[1]), "r"((a)[2]), "r"((a)[3]), "r"(b0), "r"(b1))

#define CPASYNC16(dst, src) asm volatile( \
    "cp.async.cg.shared.global [%0], [%1], 16;" :: "r"(dst), "l"(src))
#define CPCOMMIT() asm volatile("cp.async.commit_group;")
#define CPWAIT1() asm volatile("cp.async.wait_group 1;")

// ============================================================================
// K1: energyT[n][a] = K_b^T @ Q_a^T (bf16 2-term split, 3 MMA products),
//     warp-parallel column softmax, write fp16 attn plane.
// Block: (a-half, batch). 448 threads: warps 0-6 = MMA consumers
// (m32 x a112 warp tile, unchanged), warps 7-13 = producers filling the
// other stage of double-buffered split planes while consumers MMA.
// ============================================================================
#define K1_STG 53760u     // per stage: AH 0 / AL 17920 / BH 35840 / BL 44800
#define K1_SINV 107520u   // 112 floats (Csm [224][116] f32 overlays stages)
#define K1_SMEM 107968u

__global__ void __launch_bounds__(448) xattn_k1(
    const float* __restrict__ Q,    // [B, NA, DK]
    const float* __restrict__ Kb)   // [B, DK, NB]
{
    extern __shared__ char smp[];
    const u32 sb = smem_u32(smp);
    const int t = threadIdx.x, lane = t & 31, w = t >> 5;
    const int a0 = blockIdx.x * 112;
    const int b  = blockIdx.y;
    const bool consumer = (w < 7);
    const int tp = t - 224;          // producer linear id (valid when !consumer)

    const float* qb = Q + (size_t)b * NA * DK;
    const float* kb = Kb + (size_t)b * DK * NB;

    float acc[2][14][4];
    #pragma unroll
    for (int mt = 0; mt < 2; mt++)
        #pragma unroll
        for (int j = 0; j < 14; j++)
            #pragma unroll
            for (int q = 0; q < 4; q++) acc[mt][j][q] = 0.f;

    // ---- prologue: producers fill stage 0 with chunk 0
    if (!consumer) {
        char* sg = smp;   // stage 0
        #pragma unroll
        for (int i = 0; i < 32; i++) {
            float v = (tp < NB) ? kb[(size_t)i * NB + tp] : 0.f;
            unsigned short h, l;
            split2(v, h, l);
            *(unsigned short*)(sg + tp * 80 + i * 2) = h;
            *(unsigned short*)(sg + 17920u + tp * 80 + i * 2) = l;
        }
        #pragma unroll
        for (int i = 0; i < 16; i++) {
            int idx = tp + i * 224;
            int r = idx >> 5, kk = idx & 31;
            int a = a0 + r;
            float v = (a < NA) ? qb[(size_t)a * DK + kk] : 0.f;
            unsigned short h, l;
            split2(v, h, l);
            *(unsigned short*)(sg + 35840u + r * 80 + kk * 2) = h;
            *(unsigned short*)(sg + 44800u + r * 80 + kk * 2) = l;
        }
    }
    __syncthreads();

    #pragma unroll 1
    for (int kc = 0; kc < 8; kc++) {
        if (consumer) {
            // ---- MMA on stage kc&1 (overlaps producers' fill of the other)
            const u32 ahb = sb + (u32)(kc & 1) * K1_STG;
            const u32 alb = ahb + 17920u;
            const u32 bhb = ahb + 35840u;
            const u32 blb = ahb + 44800u;
            #pragma unroll
            for (int ks = 0; ks < 2; ks++) {
                u32 ah[2][4], al[2][4];
                #pragma unroll
                for (int mt = 0; mt < 2; mt++) {
                    u32 arow = w * 32 + mt * 16 + (lane & 15);
                    u32 acol = ks * 32 + ((lane >> 4) << 4);
                    LDMX4(ah[mt], ahb + arow * 80 + acol);
                    LDMX4(al[mt], alb + arow * 80 + acol);
                }
                #pragma unroll
                for (int jj = 0; jj < 7; jj++) {
                    u32 brow = jj * 16 + ((lane >> 4) << 3) + (lane & 7);
                    u32 bcol = ks * 32 + (((lane >> 3) & 1) << 4);
                    u32 bh[4], bl[4];
                    LDMX4(bh, bhb + brow * 80 + bcol);
                    LDMX4(bl, blb + brow * 80 + bcol);
                    #pragma unroll
                    for (int mt = 0; mt < 2; mt++) {
                        #pragma unroll
                        for (int hf = 0; hf < 2; hf++) {
                            int j = jj * 2 + hf;
                            MMA16816(acc[mt][j], ah[mt], bh[hf * 2], bh[hf * 2 + 1]);
                            MMA16816(acc[mt][j], ah[mt], bl[hf * 2], bl[hf * 2 + 1]);
                            MMA16816(acc[mt][j], al[mt], bh[hf * 2], bh[hf * 2 + 1]);
                        }
                    }
                }
            }
        } else if (kc < 7) {
            // ---- producers fill stage (kc+1)&1 with chunk kc+1
            const int nk = kc + 1;
            char* sg = smp + (size_t)((nk & 1)) * K1_STG;
            #pragma unroll
            for (int i = 0; i < 32; i++) {
                float v = (tp < NB) ? kb[(size_t)(nk * 32 + i) * NB + tp] : 0.f;
                unsigned short h, l;
                split2(v, h, l);
                *(unsigned short*)(sg + tp * 80 + i * 2) = h;
                *(unsigned short*)(sg + 17920u + tp * 80 + i * 2) = l;
            }
            #pragma unroll
            for (int i = 0; i < 16; i++) {
                int idx = tp + i * 224;
                int r = idx >> 5, kk = idx & 31;
                int a = a0 + r;
                float v = (a < NA) ? qb[(size_t)a * DK + nk * 32 + kk] : 0.f;
                unsigned short h, l;
                split2(v, h, l);
                *(unsigned short*)(sg + 35840u + r * 80 + kk * 2) = h;
                *(unsigned short*)(sg + 44800u + r * 80 + kk * 2) = l;
            }
        }
        __syncthreads();
    }

    // ---- epilogue: stages dead; overlay Csm [224 n][116 f32]
    float* Csm = (float*)smp;
    float* sinv = (float*)(smp + K1_SINV);
    const int g = lane >> 2, tq = lane & 3;
    if (consumer) {
        #pragma unroll
        for (int mt = 0; mt < 2; mt++)
            #pragma unroll
            for (int j = 0; j < 14; j++) {
                int row = w * 32 + mt * 16 + g;
                int col = j * 8 + tq * 2;
                *(float2*)&Csm[row * 116 + col] = make_float2(acc[mt][j][0], acc[mt][j][1]);
                *(float2*)&Csm[(row + 8) * 116 + col] = make_float2(acc[mt][j][2], acc[mt][j][3]);
            }
    }
    __syncthreads();

    // Warp-parallel column softmax: warp w -> a-cols [w*8, w*8+8). (14 warps)
    #pragma unroll 1
    for (int ci = 0; ci < 8; ci++) {
        int c = w * 8 + ci;
        float M = -1e30f;
        #pragma unroll
        for (int r = 0; r < 7; r++) {
            int n = lane + r * 32;
            if (n < NB) M = fmaxf(M, Csm[n * 116 + c]);
        }
        #pragma unroll
        for (int o = 16; o; o >>= 1)
            M = fmaxf(M, __shfl_xor_sync(0xFFFFFFFFu, M, o));
        float S = 0.f;
        #pragma unroll
        for (int r = 0; r < 7; r++) {
            int n = lane + r * 32;
            if (n < NB) {
                float e = __expf(SMOOTH_F * (Csm[n * 116 + c] - M));
                Csm[n * 116 + c] = e;
                S += e;
            }
        }
        #pragma unroll
        for (int o = 16; o; o >>= 1)
            S += __shfl_xor_sync(0xFFFFFFFFu, S, o);
        if (lane == 0)
            sinv[c] = (a0 + c < NA) ? (1.f / S) : 0.f;
    }
    __syncthreads();

    // Write fp16 attn plane (coalesced rows; zero rows for n >= 196).
    if (lane < 28) {
        float4 s4 = *(float4*)&sinv[lane * 4];
        for (int r = w; r < NP; r += 14) {
            uint2 hh = make_uint2(0u, 0u);
            if (r < NB) {
                float4 p = *(float4*)&Csm[r * 116 + lane * 4];
                unsigned short h0 = __half_as_ushort(__float2half_rn(p.x * s4.x));
                unsigned short h1 = __half_as_ushort(__float2half_rn(p.y * s4.y));
                unsigned short h2 = __half_as_ushort(__float2half_rn(p.z * s4.z));
                unsigned short h3 = __half_as_ushort(__float2half_rn(p.w * s4.w));
                hh = make_uint2((u32)h0 | ((u32)h1 << 16), (u32)h2 | ((u32)h3 << 16));
            }
            size_t off = (size_t)(b * NP + r) * NP + a0 + lane * 4;
            *(uint2*)(g_ah + off) = hh;
        }
    }
}

// ============================================================================
// K2: out = gamma + V_a @ attn + V_b  (fp16: V_a 2-plane split x attn 1 plane).
// Block: 128 threads = 4 M-warps, tile m128 x n112 (n split across blocks).
// Warp tile m32 x n112; 3 CTAs/SM. (Unchanged from round 11 — 234 µs.)
// ============================================================================
#define K2_ASTG 20480u                // per stage: 2 planes x (128 x 80B)
#define K2_B0   40960u                // B stages: [112 n][32 k] fp16, 80B stride
#define K2_BSTAGE 8960u               // single plane per stage
#define K2_SMEM 58880u

__global__ void __launch_bounds__(128, 3) xattn_k2(
    const float* __restrict__ VA,   // [B, DIM, NA]
    const float* __restrict__ VB,   // [B, DIM, NB]
    const float* __restrict__ G,
    float* __restrict__ O)          // [B, DIM, NB]
{
    extern __shared__ char smp[];
    const u32 sb = smem_u32(smp);
    const int t = threadIdx.x, lane = t & 31, w = t >> 5;
    const int m0  = (blockIdx.x >> 1) * 128;
    const int nb0 = (blockIdx.x & 1) * 112;
    const int b   = blockIdx.y;

    const float* va = VA + ((size_t)b * DIM + m0) * NA;
    const char* ghp = (const char*)g_ah;

    // ---- prologue: B chunk 0 via cp.async, A chunk 0 split-stored to stage 0
    {
        #pragma unroll
        for (int i = 0; i < 4; i++) {
            int idx = t + i * 128;
            if (idx < 448) {
                int n = idx >> 2, c = idx & 3;
                u32 dst = sb + K2_B0 + n * 80 + c * 16;
                const char* src = ghp + ((size_t)(b * NP + nb0 + n) * NP + c * 8) * 2;
                CPASYNC16(dst, src);
            }
        }
        CPCOMMIT();
        #pragma unroll
        for (int i = 0; i < 8; i++) {
            int idx = t + i * 128;
            int row = idx >> 3, q4 = idx & 7;
            int col = q4 * 4;
            float4 v = make_float4(0.f, 0.f, 0.f, 0.f);
            if (col < NA) v = *(const float4*)(va + (size_t)row * NA + col);
            unsigned short h[4], l[4];
            split2h(v.x, h[0], l[0]); split2h(v.y, h[1], l[1]);
            split2h(v.z, h[2], l[2]); split2h(v.w, h[3], l[3]);
            *(uint2*)(smp + row * 80 + col * 2) =
                make_uint2((u32)h[0] | ((u32)h[1] << 16), (u32)h[2] | ((u32)h[3] << 16));
            *(uint2*)(smp + 10240u + row * 80 + col * 2) =
                make_uint2((u32)l[0] | ((u32)l[1] << 16), (u32)l[2] | ((u32)l[3] << 16));
        }
    }

    float acc[2][14][4];
    #pragma unroll
    for (int mt = 0; mt < 2; mt++)
        #pragma unroll
        for (int j = 0; j < 14; j++)
            #pragma unroll
            for (int q = 0; q < 4; q++) acc[mt][j][q] = 0.f;

    #pragma unroll 1
    for (int kc = 0; kc < 7; kc++) {
        if (kc < 6) {   // prefetch next B chunk + fill next A stage
            const int nk = kc + 1, st = nk & 1;
            #pragma unroll
            for (int i = 0; i < 4; i++) {
                int idx = t + i * 128;
                if (idx < 448) {
                    int n = idx >> 2, c = idx & 3;
                    u32 dst = sb + K2_B0 + st * K2_BSTAGE + n * 80 + c * 16;
                    const char* src = ghp +
                        ((size_t)(b * NP + nb0 + n) * NP + nk * 32 + c * 8) * 2;
                    CPASYNC16(dst, src);
                }
            }
            #pragma unroll
            for (int i = 0; i < 8; i++) {
                int idx = t + i * 128;
                int row = idx >> 3, q4 = idx & 7;
                int col = q4 * 4;
                int ac = nk * 32 + col;
                float4 v = make_float4(0.f, 0.f, 0.f, 0.f);
                if (ac < NA) v = *(const float4*)(va + (size_t)row * NA + ac);
                unsigned short h[4], l[4];
                split2h(v.x, h[0], l[0]); split2h(v.y, h[1], l[1]);
                split2h(v.z, h[2], l[2]); split2h(v.w, h[3], l[3]);
                *(uint2*)(smp + st * K2_ASTG + row * 80 + col * 2) =
                    make_uint2((u32)h[0] | ((u32)h[1] << 16), (u32)h[2] | ((u32)h[3] << 16));
                *(uint2*)(smp + st * K2_ASTG + 10240u + row * 80 + col * 2) =
                    make_uint2((u32)l[0] | ((u32)l[1] << 16), (u32)l[2] | ((u32)l[3] << 16));
            }
        }
        CPCOMMIT();
        CPWAIT1();
        __syncthreads();

        const u32 ahb = sb + (kc & 1) * K2_ASTG;
        const u32 alb = ahb + 10240u;
        const u32 bhb = sb + K2_B0 + (kc & 1) * K2_BSTAGE;

        #pragma unroll
        for (int ks = 0; ks < 2; ks++) {
            u32 ah[2][4], al[2][4];
            #pragma unroll
            for (int mt = 0; mt < 2; mt++) {
                u32 arow = w * 32 + mt * 16 + (lane & 15);
                u32 acol = ks * 32 + ((lane >> 4) << 4);
                LDMX4(ah[mt], ahb + arow * 80 + acol);
                LDMX4(al[mt], alb + arow * 80 + acol);
            }
            #pragma unroll
            for (int jj = 0; jj < 7; jj++) {
                u32 brow = jj * 16 + ((lane >> 4) << 3) + (lane & 7);
                u32 bcol = ks * 32 + (((lane >> 3) & 1) << 4);
                u32 bh[4];
                LDMX4(bh, bhb + brow * 80 + bcol);
                #pragma unroll
                for (int mt = 0; mt < 2; mt++) {
                    #pragma unroll
                    for (int hf = 0; hf < 2; hf++) {
                        int j = jj * 2 + hf;
                        MMAF16816(acc[mt][j], ah[mt], bh[hf * 2], bh[hf * 2 + 1]);
                        MMAF16816(acc[mt][j], al[mt], bh[hf * 2], bh[hf * 2 + 1]);
                    }
                }
            }
        }
        __syncthreads();
    }

    // Epilogue: out = gamma + acc + V_b (guarded float2 stores)
    const float gam = G[0];
    const int g = lane >> 2, tq = lane & 3;
    #pragma unroll
    for (int mt = 0; mt < 2; mt++)
        #pragma unroll
        for (int j = 0; j < 14; j++) {
            int n = nb0 + j * 8 + tq * 2;
            if (n < NB) {
                int row = m0 + w * 32 + mt * 16 + g;
                size_t o0 = ((size_t)(b * DIM + row)) * NB + n;
                size_t o1 = o0 + (size_t)8 * NB;
                float2 v0 = *(const float2*)(VB + o0);
                float2 v1 = *(const float2*)(VB + o1);
                *(float2*)(O + o0) = make_float2(gam + acc[mt][j][0] + v0.x,
                                                 gam + acc[mt][j][1] + v0.y);
                *(float2*)(O + o1) = make_float2(gam + acc[mt][j][2] + v1.x,
                                                 gam + acc[mt][j][3] + v1.y);
            }
        }
}

// ============================================================================
extern "C" void kernel_launch(void* const* d_in, const int* in_sizes, int n_in,
                              void* d_out, int out_size)
{
    const float* query_a = (const float*)d_in[0];
    const float* value_a = (const float*)d_in[1];
    const float* key_b   = (const float*)d_in[2];
    const float* value_b = (const float*)d_in[3];
    const float* gamma   = (const float*)d_in[4];
    float* out = (float*)d_out;

    cudaFuncSetAttribute(xattn_k1, cudaFuncAttributeMaxDynamicSharedMemorySize, K1_SMEM);
    cudaFuncSetAttribute(xattn_k2, cudaFuncAttributeMaxDynamicSharedMemorySize, K2_SMEM);

    xattn_k1<<<dim3(2, BATCH), 448, K1_SMEM>>>(query_a, key_b);
    xattn_k2<<<dim3(16, BATCH), 128, K2_SMEM>>>(value_a, value_b, gamma, out);
}

// round 14
// speedup vs baseline: 1.6233x; 1.6233x over previous
#include <cuda_runtime.h>
#include <cuda_bf16.h>
#include <cuda_fp16.h>
#include <cstdint>

#define BATCH 256
#define NA 196
#define NB 196
#define DK 256
#define DIM 1024
#define SMOOTH_F 4.0f
#define NP 224   // padded n / a dims

// Attention weights, transposed [b][n][a], single fp16 plane, zero-padded.
__device__ unsigned short g_ah[(size_t)BATCH * NP * NP];

typedef unsigned int u32;

__device__ __forceinline__ u32 smem_u32(const void* p) {
    u32 a;
    asm("{ .reg .u64 t; cvta.to.shared.u64 t, %1; cvt.u32.u64 %0, t; }" : "=r"(a) : "l"(p));
    return a;
}
// bf16 2-term split (k1 energy GEMM — softmax-sensitive, keep high precision)
__device__ __forceinline__ void split2(float x, unsigned short& h, unsigned short& l) {
    __nv_bfloat16 hb = __float2bfloat16_rn(x);
    float r = x - __bfloat162float(hb);
    h = __bfloat16_as_ushort(hb);
    l = __bfloat16_as_ushort(__float2bfloat16_rn(r));
}
// fp16 2-term split (k2 V_a — exact to ~2^-22)
__device__ __forceinline__ void split2h(float x, unsigned short& h, unsigned short& l) {
    __half hb = __float2half_rn(x);
    float r = x - __half2float(hb);
    h = __half_as_ushort(hb);
    l = __half_as_ushort(__float2half_rn(r));
}

#define LDMX4(r, a) asm volatile( \
    "ldmatrix.sync.aligned.m8n8.x4.shared.b16 {%0,%1,%2,%3}, [%4];" \
    : "=r"((r)[0]), "=r"((r)[1]), "=r"((r)[2]), "=r"((r)[3]) : "r"(a))

#define MMA16816(d, a, b0, b1) asm volatile( \
    "mma.sync.aligned.m16n8k16.row.col.f32.bf16.bf16.f32 " \
    "{%0,%1,%2,%3}, {%4,%5,%6,%7}, {%8,%9}, {%0,%1,%2,%3};" \
    : "+f"((d)[0]), "+f"((d)[1]), "+f"((d)[2]), "+f"((d)[3]) \
    : "r"((a)[0]), "r"((a)[1]), "r"((a)[2]), "r"((a)[3]), "r"(b0), "r"(b1))

#define MMAF16816(d, a, b0, b1) asm volatile( \
    "mma.sync.aligned.m16n8k16.row.col.f32.f16.f16.f32 " \
    "{%0,%1,%2,%3}, {%4,%5,%6,%7}, {%8,%9}, {%0,%1,%2,%3};" \
    : "+f"((d)[0]), "+f"((d)[1]), "+f"((d)[2]), "+f"((d)[3]) \
    : "r"((a)[0]), "r"((a)[1]), "r"((a)[2]), "r"((a)[3]), "r"(b0), "r"(b1))

#define CPASYNC16(dst, src) asm volatile( \
    "cp.async.cg.shared.global [%0], [%1], 16;" :: "r"(dst), "l"(src))
#define CPCOMMIT() asm volatile("cp.async.commit_group;")
#define CPWAIT1() asm volatile("cp.async.wait_group 1;")
#define CPWAIT0() asm volatile("cp.async.wait_group 0;")

// ============================================================================
// K1: energyT[n][a] = K_b^T @ Q_a^T (bf16 2-term split, 3 MMA products),
//     warp-parallel column softmax, write fp16 attn plane.
// Block: (a-half, batch). 224 threads = 7 warps; warp = 32 n-rows x 112 a-cols.
// Raw f32 K/Q chunks cp.async double-buffered (gmem latency overlapped with
// MMA); fast smem->smem split-convert feeds single-buffered bf16 planes.
// ============================================================================
#define K1_RK0 0u          // raw K stage: [32 k][224 n] f32, 896B row stride
#define K1_RKS 28672u
#define K1_RQ0 57344u      // raw Q stage: [112 a][32 k] f32, 128B row stride
#define K1_RQS 14336u
#define K1_PL  86016u      // planes: AH +0 / AL +17920 / BH +35840 / BL +44800
#define K1_SINV 139776u    // 112 floats (Csm [224][116] f32 overlays everything)
#define K1_SMEM 140224u

__global__ void __launch_bounds__(224) xattn_k1(
    const float* __restrict__ Q,    // [B, NA, DK]
    const float* __restrict__ Kb)   // [B, DK, NB]
{
    extern __shared__ char smp[];
    const u32 sb = smem_u32(smp);
    const int t = threadIdx.x, lane = t & 31, w = t >> 5;
    const int a0 = blockIdx.x * 112;
    const int b  = blockIdx.y;

    const char* qb = (const char*)(Q + (size_t)b * NA * DK);
    const char* kb = (const char*)(Kb + (size_t)b * DK * NB);

    // ---- pre-zero pad regions of BOTH raw stages (written once, never dirtied)
    // K raw: cols n in [196,224) of all 32 rows; Q raw: rows a-local >= NA-a0.
    for (int s = 0; s < 2; s++) {
        char* rk = smp + K1_RK0 + s * K1_RKS;
        for (int idx = t; idx < 32 * 28; idx += 224) {
            int row = idx / 28, c = idx % 28;
            *(float*)(rk + row * 896 + (196 + c) * 4) = 0.f;
        }
        char* rq = smp + K1_RQ0 + s * K1_RQS;
        for (int idx = t; idx < 28 * 32; idx += 224) {
            int row = 84 + idx / 32, kk = idx % 32;
            *(float*)(rq + row * 128 + kk * 4) = 0.f;
        }
    }

    // ---- prefetch chunk 0 into stage 0
    {
        #pragma unroll
        for (int i = 0; i < 7; i++) {          // K: 32 rows x 49 x 16B
            int idx = t + i * 224;
            int row = idx / 49, c = idx % 49;
            CPASYNC16(sb + K1_RK0 + row * 896 + c * 16,
                      kb + (size_t)row * NB * 4 + c * 16);
        }
        #pragma unroll
        for (int i = 0; i < 4; i++) {          // Q: 112 rows x 8 x 16B
            int idx = t + i * 224;
            int row = idx >> 3, c = idx & 7;
            if (a0 + row < NA)
                CPASYNC16(sb + K1_RQ0 + row * 128 + c * 16,
                          qb + (size_t)(a0 + row) * DK * 4 + c * 16);
        }
        CPCOMMIT();
    }

    float acc[2][14][4];
    #pragma unroll
    for (int mt = 0; mt < 2; mt++)
        #pragma unroll
        for (int j = 0; j < 14; j++)
            #pragma unroll
            for (int q = 0; q < 4; q++) acc[mt][j][q] = 0.f;

    #pragma unroll 1
    for (int kc = 0; kc < 8; kc++) {
        const int st = kc & 1;
        if (kc < 7) {   // prefetch chunk kc+1 into the other stage
            const int nk = kc + 1, ns = nk & 1;
            #pragma unroll
            for (int i = 0; i < 7; i++) {
                int idx = t + i * 224;
                int row = idx / 49, c = idx % 49;
                CPASYNC16(sb + K1_RK0 + ns * K1_RKS + row * 896 + c * 16,
                          kb + (size_t)(nk * 32 + row) * NB * 4 + c * 16);
            }
            #pragma unroll
            for (int i = 0; i < 4; i++) {
                int idx = t + i * 224;
                int row = idx >> 3, c = idx & 7;
                if (a0 + row < NA)
                    CPASYNC16(sb + K1_RQ0 + ns * K1_RQS + row * 128 + c * 16,
                              qb + (size_t)(a0 + row) * DK * 4 + nk * 128 + c * 16);
            }
            CPCOMMIT();
            CPWAIT1();
        } else {
            CPWAIT0();
        }
        __syncthreads();   // raw chunk kc visible; previous MMA done with planes

        // ---- convert raw(st) -> planes (smem->smem, conflict-free)
        {
            const char* rk = smp + K1_RK0 + st * K1_RKS;
            #pragma unroll
            for (int k = 0; k < 32; k++) {
                float v = *(const float*)(rk + k * 896 + t * 4);
                unsigned short h, l;
                split2(v, h, l);
                *(unsigned short*)(smp + K1_PL + t * 80 + k * 2) = h;
                *(unsigned short*)(smp + K1_PL + 17920u + t * 80 + k * 2) = l;
            }
            const char* rq = smp + K1_RQ0 + st * K1_RQS;
            #pragma unroll
            for (int i = 0; i < 16; i++) {
                int idx = t + i * 224;
                int r = idx >> 5, kk = idx & 31;
                float v = *(const float*)(rq + r * 128 + kk * 4);
                unsigned short h, l;
                split2(v, h, l);
                *(unsigned short*)(smp + K1_PL + 35840u + r * 80 + kk * 2) = h;
                *(unsigned short*)(smp + K1_PL + 44800u + r * 80 + kk * 2) = l;
            }
        }
        __syncthreads();

        // ---- MMA on planes
        const u32 ahb = sb + K1_PL;
        const u32 alb = ahb + 17920u;
        const u32 bhb = ahb + 35840u;
        const u32 blb = ahb + 44800u;
        #pragma unroll
        for (int ks = 0; ks < 2; ks++) {
            u32 ah[2][4], al[2][4];
            #pragma unroll
            for (int mt = 0; mt < 2; mt++) {
                u32 arow = w * 32 + mt * 16 + (lane & 15);
                u32 acol = ks * 32 + ((lane >> 4) << 4);
                LDMX4(ah[mt], ahb + arow * 80 + acol);
                LDMX4(al[mt], alb + arow * 80 + acol);
            }
            #pragma unroll
            for (int jj = 0; jj < 7; jj++) {
                u32 brow = jj * 16 + ((lane >> 4) << 3) + (lane & 7);
                u32 bcol = ks * 32 + (((lane >> 3) & 1) << 4);
                u32 bh[4], bl[4];
                LDMX4(bh, bhb + brow * 80 + bcol);
                LDMX4(bl, blb + brow * 80 + bcol);
                #pragma unroll
                for (int mt = 0; mt < 2; mt++) {
                    #pragma unroll
                    for (int hf = 0; hf < 2; hf++) {
                        int j = jj * 2 + hf;
                        MMA16816(acc[mt][j], ah[mt], bh[hf * 2], bh[hf * 2 + 1]);
                        MMA16816(acc[mt][j], ah[mt], bl[hf * 2], bl[hf * 2 + 1]);
                        MMA16816(acc[mt][j], al[mt], bh[hf * 2], bh[hf * 2 + 1]);
                    }
                }
            }
        }
    }
    __syncthreads();   // staging dead; reuse as Csm [224 n][116 f32]

    float* Csm = (float*)smp;
    float* sinv = (float*)(smp + K1_SINV);
    const int g = lane >> 2, tq = lane & 3;
    #pragma unroll
    for (int mt = 0; mt < 2; mt++)
        #pragma unroll
        for (int j = 0; j < 14; j++) {
            int row = w * 32 + mt * 16 + g;
            int col = j * 8 + tq * 2;
            *(float2*)&Csm[row * 116 + col] = make_float2(acc[mt][j][0], acc[mt][j][1]);
            *(float2*)&Csm[(row + 8) * 116 + col] = make_float2(acc[mt][j][2], acc[mt][j][3]);
        }
    __syncthreads();

    // Warp-parallel column softmax: warp w -> a-cols [w*16, w*16+16).
    #pragma unroll 1
    for (int ci = 0; ci < 16; ci++) {
        int c = w * 16 + ci;
        float M = -1e30f;
        #pragma unroll
        for (int r = 0; r < 7; r++) {
            int n = lane + r * 32;
            if (n < NB) M = fmaxf(M, Csm[n * 116 + c]);
        }
        #pragma unroll
        for (int o = 16; o; o >>= 1)
            M = fmaxf(M, __shfl_xor_sync(0xFFFFFFFFu, M, o));
        float S = 0.f;
        #pragma unroll
        for (int r = 0; r < 7; r++) {
            int n = lane + r * 32;
            if (n < NB) {
                float e = __expf(SMOOTH_F * (Csm[n * 116 + c] - M));
                Csm[n * 116 + c] = e;
                S += e;
            }
        }
        #pragma unroll
        for (int o = 16; o; o >>= 1)
            S += __shfl_xor_sync(0xFFFFFFFFu, S, o);
        if (lane == 0)
            sinv[c] = (a0 + c < NA) ? (1.f / S) : 0.f;
    }
    __syncthreads();

    // Write fp16 attn plane (coalesced rows; zero rows for n >= 196).
    if (lane < 28) {
        float4 s4 = *(float4*)&sinv[lane * 4];
        for (int r = w; r < NP; r += 7) {
            uint2 hh = make_uint2(0u, 0u);
            if (r < NB) {
                float4 p = *(float4*)&Csm[r * 116 + lane * 4];
                unsigned short h0 = __half_as_ushort(__float2half_rn(p.x * s4.x));
                unsigned short h1 = __half_as_ushort(__float2half_rn(p.y * s4.y));
                unsigned short h2 = __half_as_ushort(__float2half_rn(p.z * s4.z));
                unsigned short h3 = __half_as_ushort(__float2half_rn(p.w * s4.w));
                hh = make_uint2((u32)h0 | ((u32)h1 << 16), (u32)h2 | ((u32)h3 << 16));
            }
            size_t off = (size_t)(b * NP + r) * NP + a0 + lane * 4;
            *(uint2*)(g_ah + off) = hh;
        }
    }
}

// ============================================================================
// K2: out = gamma + V_a @ attn + V_b  (fp16: V_a 2-plane split x attn 1 plane).
// Block: 128 threads = 4 M-warps, tile m128 x n112 (n split across blocks).
// Warp tile m32 x n112; 3 CTAs/SM. (Unchanged — 234 µs at sane clocks.)
// ============================================================================
#define K2_ASTG 20480u                // per stage: 2 planes x (128 x 80B)
#define K2_B0   40960u                // B stages: [112 n][32 k] fp16, 80B stride
#define K2_BSTAGE 8960u               // single plane per stage
#define K2_SMEM 58880u

__global__ void __launch_bounds__(128, 3) xattn_k2(
    const float* __restrict__ VA,   // [B, DIM, NA]
    const float* __restrict__ VB,   // [B, DIM, NB]
    const float* __restrict__ G,
    float* __restrict__ O)          // [B, DIM, NB]
{
    extern __shared__ char smp[];
    const u32 sb = smem_u32(smp);
    const int t = threadIdx.x, lane = t & 31, w = t >> 5;
    const int m0  = (blockIdx.x >> 1) * 128;
    const int nb0 = (blockIdx.x & 1) * 112;
    const int b   = blockIdx.y;

    const float* va = VA + ((size_t)b * DIM + m0) * NA;
    const char* ghp = (const char*)g_ah;

    // ---- prologue: B chunk 0 via cp.async, A chunk 0 split-stored to stage 0
    {
        #pragma unroll
        for (int i = 0; i < 4; i++) {
            int idx = t + i * 128;
            if (idx < 448) {
                int n = idx >> 2, c = idx & 3;
                u32 dst = sb + K2_B0 + n * 80 + c * 16;
                const char* src = ghp + ((size_t)(b * NP + nb0 + n) * NP + c * 8) * 2;
                CPASYNC16(dst, src);
            }
        }
        CPCOMMIT();
        #pragma unroll
        for (int i = 0; i < 8; i++) {
            int idx = t + i * 128;
            int row = idx >> 3, q4 = idx & 7;
            int col = q4 * 4;
            float4 v = make_float4(0.f, 0.f, 0.f, 0.f);
            if (col < NA) v = *(const float4*)(va + (size_t)row * NA + col);
            unsigned short h[4], l[4];
            split2h(v.x, h[0], l[0]); split2h(v.y, h[1], l[1]);
            split2h(v.z, h[2], l[2]); split2h(v.w, h[3], l[3]);
            *(uint2*)(smp + row * 80 + col * 2) =
                make_uint2((u32)h[0] | ((u32)h[1] << 16), (u32)h[2] | ((u32)h[3] << 16));
            *(uint2*)(smp + 10240u + row * 80 + col * 2) =
                make_uint2((u32)l[0] | ((u32)l[1] << 16), (u32)l[2] | ((u32)l[3] << 16));
        }
    }

    float acc[2][14][4];
    #pragma unroll
    for (int mt = 0; mt < 2; mt++)
        #pragma unroll
        for (int j = 0; j < 14; j++)
            #pragma unroll
            for (int q = 0; q < 4; q++) acc[mt][j][q] = 0.f;

    #pragma unroll 1
    for (int kc = 0; kc < 7; kc++) {
        if (kc < 6) {   // prefetch next B chunk + fill next A stage
            const int nk = kc + 1, st = nk & 1;
            #pragma unroll
            for (int i = 0; i < 4; i++) {
                int idx = t + i * 128;
                if (idx < 448) {
                    int n = idx >> 2, c = idx & 3;
                    u32 dst = sb + K2_B0 + st * K2_BSTAGE + n * 80 + c * 16;
                    const char* src = ghp +
                        ((size_t)(b * NP + nb0 + n) * NP + nk * 32 + c * 8) * 2;
                    CPASYNC16(dst, src);
                }
            }
            #pragma unroll
            for (int i = 0; i < 8; i++) {
                int idx = t + i * 128;
                int row = idx >> 3, q4 = idx & 7;
                int col = q4 * 4;
                int ac = nk * 32 + col;
                float4 v = make_float4(0.f, 0.f, 0.f, 0.f);
                if (ac < NA) v = *(const float4*)(va + (size_t)row * NA + ac);
                unsigned short h[4], l[4];
                split2h(v.x, h[0], l[0]); split2h(v.y, h[1], l[1]);
                split2h(v.z, h[2], l[2]); split2h(v.w, h[3], l[3]);
                *(uint2*)(smp + st * K2_ASTG + row * 80 + col * 2) =
                    make_uint2((u32)h[0] | ((u32)h[1] << 16), (u32)h[2] | ((u32)h[3] << 16));
                *(uint2*)(smp + st * K2_ASTG + 10240u + row * 80 + col * 2) =
                    make_uint2((u32)l[0] | ((u32)l[1] << 16), (u32)l[2] | ((u32)l[3] << 16));
            }
        }
        CPCOMMIT();
        CPWAIT1();
        __syncthreads();

        const u32 ahb = sb + (kc & 1) * K2_ASTG;
        const u32 alb = ahb + 10240u;
        const u32 bhb = sb + K2_B0 + (kc & 1) * K2_BSTAGE;

        #pragma unroll
        for (int ks = 0; ks < 2; ks++) {
            u32 ah[2][4], al[2][4];
            #pragma unroll
            for (int mt = 0; mt < 2; mt++) {
                u32 arow = w * 32 + mt * 16 + (lane & 15);
                u32 acol = ks * 32 + ((lane >> 4) << 4);
                LDMX4(ah[mt], ahb + arow * 80 + acol);
                LDMX4(al[mt], alb + arow * 80 + acol);
            }
            #pragma unroll
            for (int jj = 0; jj < 7; jj++) {
                u32 brow = jj * 16 + ((lane >> 4) << 3) + (lane & 7);
                u32 bcol = ks * 32 + (((lane >> 3) & 1) << 4);
                u32 bh[4];
                LDMX4(bh, bhb + brow * 80 + bcol);
                #pragma unroll
                for (int mt = 0; mt < 2; mt++) {
                    #pragma unroll
                    for (int hf = 0; hf < 2; hf++) {
                        int j = jj * 2 + hf;
                        MMAF16816(acc[mt][j], ah[mt], bh[hf * 2], bh[hf * 2 + 1]);
                        MMAF16816(acc[mt][j], al[mt], bh[hf * 2], bh[hf * 2 + 1]);
                    }
                }
            }
        }
        __syncthreads();
    }

    // Epilogue: out = gamma + acc + V_b (guarded float2 stores)
    const float gam = G[0];
    const int g = lane >> 2, tq = lane & 3;
    #pragma unroll
    for (int mt = 0; mt < 2; mt++)
        #pragma unroll
        for (int j = 0; j < 14; j++) {
            int n = nb0 + j * 8 + tq * 2;
            if (n < NB) {
                int row = m0 + w * 32 + mt * 16 + g;
                size_t o0 = ((size_t)(b * DIM + row)) * NB + n;
                size_t o1 = o0 + (size_t)8 * NB;
                float2 v0 = *(const float2*)(VB + o0);
                float2 v1 = *(const float2*)(VB + o1);
                *(float2*)(O + o0) = make_float2(gam + acc[mt][j][0] + v0.x,
                                                 gam + acc[mt][j][1] + v0.y);
                *(float2*)(O + o1) = make_float2(gam + acc[mt][j][2] + v1.x,
                                                 gam + acc[mt][j][3] + v1.y);
            }
        }
}

// ============================================================================
extern "C" void kernel_launch(void* const* d_in, const int* in_sizes, int n_in,
                              void* d_out, int out_size)
{
    const float* query_a = (const float*)d_in[0];
    const float* value_a = (const float*)d_in[1];
    const float* key_b   = (const float*)d_in[2];
    const float* value_b = (const float*)d_in[3];
    const float* gamma   = (const float*)d_in[4];
    float* out = (float*)d_out;

    cudaFuncSetAttribute(xattn_k1, cudaFuncAttributeMaxDynamicSharedMemorySize, K1_SMEM);
    cudaFuncSetAttribute(xattn_k2, cudaFuncAttributeMaxDynamicSharedMemorySize, K2_SMEM);

    xattn_k1<<<dim3(2, BATCH), 224, K1_SMEM>>>(query_a, key_b);
    xattn_k2<<<dim3(16, BATCH), 128, K2_SMEM>>>(value_a, value_b, gamma, out);
}

// round 15
// speedup vs baseline: 1.7489x; 1.0773x over previous
#include <cuda_runtime.h>
#include <cuda_bf16.h>
#include <cuda_fp16.h>
#include <cstdint>

#define BATCH 256
#define NA 196
#define NB 196
#define DK 256
#define DIM 1024
#define SMOOTH_F 4.0f
#define NP 224   // padded n / a dims

// Attention weights, transposed [b][n][a], single fp16 plane, zero-padded.
__device__ unsigned short g_ah[(size_t)BATCH * NP * NP];

typedef unsigned int u32;

__device__ __forceinline__ u32 smem_u32(const void* p) {
    u32 a;
    asm("{ .reg .u64 t; cvta.to.shared.u64 t, %1; cvt.u32.u64 %0, t; }" : "=r"(a) : "l"(p));
    return a;
}
// bf16 2-term split (k1 energy GEMM — softmax-sensitive, keep high precision)
__device__ __forceinline__ void split2(float x, unsigned short& h, unsigned short& l) {
    __nv_bfloat16 hb = __float2bfloat16_rn(x);
    float r = x - __bfloat162float(hb);
    h = __bfloat16_as_ushort(hb);
    l = __bfloat16_as_ushort(__float2bfloat16_rn(r));
}

#define LDMX4(r, a) asm volatile( \
    "ldmatrix.sync.aligned.m8n8.x4.shared.b16 {%0,%1,%2,%3}, [%4];" \
    : "=r"((r)[0]), "=r"((r)[1]), "=r"((r)[2]), "=r"((r)[3]) : "r"(a))

#define MMA16816(d, a, b0, b1) asm volatile( \
    "mma.sync.aligned.m16n8k16.row.col.f32.bf16.bf16.f32 " \
    "{%0,%1,%2,%3}, {%4,%5,%6,%7}, {%8,%9}, {%0,%1,%2,%3};" \
    : "+f"((d)[0]), "+f"((d)[1]), "+f"((d)[2]), "+f"((d)[3]) \
    : "r"((a)[0]), "r"((a)[1]), "r"((a)[2]), "r"((a)[3]), "r"(b0), "r"(b1))

#define MMAF16816(d, a, b0, b1) asm volatile( \
    "mma.sync.aligned.m16n8k16.row.col.f32.f16.f16.f32 " \
    "{%0,%1,%2,%3}, {%4,%5,%6,%7}, {%8,%9}, {%0,%1,%2,%3};" \
    : "+f"((d)[0]), "+f"((d)[1]), "+f"((d)[2]), "+f"((d)[3]) \
    : "r"((a)[0]), "r"((a)[1]), "r"((a)[2]), "r"((a)[3]), "r"(b0), "r"(b1))

#define CPASYNC16(dst, src) asm volatile( \
    "cp.async.cg.shared.global [%0], [%1], 16;" :: "r"(dst), "l"(src))
#define CPCOMMIT() asm volatile("cp.async.commit_group;")
#define CPWAIT1() asm volatile("cp.async.wait_group 1;")
#define CPWAIT0() asm volatile("cp.async.wait_group 0;")

// ============================================================================
// K1: energyT[n][a] = K_b^T @ Q_a^T (bf16 2-term split, 3 MMA products),
//     warp-parallel column softmax, write fp16 attn plane.
// Block: (a-half, batch). 224 threads = 7 warps; warp = 32 n-rows x 112 a-cols.
// Raw f32 K/Q chunks cp.async double-buffered; smem->smem split-convert.
// (Unchanged from round 14 — 137 µs.)
// ============================================================================
#define K1_RK0 0u          // raw K stage: [32 k][224 n] f32, 896B row stride
#define K1_RKS 28672u
#define K1_RQ0 57344u      // raw Q stage: [112 a][32 k] f32, 128B row stride
#define K1_RQS 14336u
#define K1_PL  86016u      // planes: AH +0 / AL +17920 / BH +35840 / BL +44800
#define K1_SINV 139776u    // 112 floats (Csm [224][116] f32 overlays everything)
#define K1_SMEM 140224u

__global__ void __launch_bounds__(224) xattn_k1(
    const float* __restrict__ Q,    // [B, NA, DK]
    const float* __restrict__ Kb)   // [B, DK, NB]
{
    extern __shared__ char smp[];
    const u32 sb = smem_u32(smp);
    const int t = threadIdx.x, lane = t & 31, w = t >> 5;
    const int a0 = blockIdx.x * 112;
    const int b  = blockIdx.y;

    const char* qb = (const char*)(Q + (size_t)b * NA * DK);
    const char* kb = (const char*)(Kb + (size_t)b * DK * NB);

    // ---- pre-zero pad regions of BOTH raw stages
    for (int s = 0; s < 2; s++) {
        char* rk = smp + K1_RK0 + s * K1_RKS;
        for (int idx = t; idx < 32 * 28; idx += 224) {
            int row = idx / 28, c = idx % 28;
            *(float*)(rk + row * 896 + (196 + c) * 4) = 0.f;
        }
        char* rq = smp + K1_RQ0 + s * K1_RQS;
        for (int idx = t; idx < 28 * 32; idx += 224) {
            int row = 84 + idx / 32, kk = idx % 32;
            *(float*)(rq + row * 128 + kk * 4) = 0.f;
        }
    }

    // ---- prefetch chunk 0 into stage 0
    {
        #pragma unroll
        for (int i = 0; i < 7; i++) {          // K: 32 rows x 49 x 16B
            int idx = t + i * 224;
            int row = idx / 49, c = idx % 49;
            CPASYNC16(sb + K1_RK0 + row * 896 + c * 16,
                      kb + (size_t)row * NB * 4 + c * 16);
        }
        #pragma unroll
        for (int i = 0; i < 4; i++) {          // Q: 112 rows x 8 x 16B
            int idx = t + i * 224;
            int row = idx >> 3, c = idx & 7;
            if (a0 + row < NA)
                CPASYNC16(sb + K1_RQ0 + row * 128 + c * 16,
                          qb + (size_t)(a0 + row) * DK * 4 + c * 16);
        }
        CPCOMMIT();
    }

    float acc[2][14][4];
    #pragma unroll
    for (int mt = 0; mt < 2; mt++)
        #pragma unroll
        for (int j = 0; j < 14; j++)
            #pragma unroll
            for (int q = 0; q < 4; q++) acc[mt][j][q] = 0.f;

    #pragma unroll 1
    for (int kc = 0; kc < 8; kc++) {
        const int st = kc & 1;
        if (kc < 7) {
            const int nk = kc + 1, ns = nk & 1;
            #pragma unroll
            for (int i = 0; i < 7; i++) {
                int idx = t + i * 224;
                int row = idx / 49, c = idx % 49;
                CPASYNC16(sb + K1_RK0 + ns * K1_RKS + row * 896 + c * 16,
                          kb + (size_t)(nk * 32 + row) * NB * 4 + c * 16);
            }
            #pragma unroll
            for (int i = 0; i < 4; i++) {
                int idx = t + i * 224;
                int row = idx >> 3, c = idx & 7;
                if (a0 + row < NA)
                    CPASYNC16(sb + K1_RQ0 + ns * K1_RQS + row * 128 + c * 16,
                              qb + (size_t)(a0 + row) * DK * 4 + nk * 128 + c * 16);
            }
            CPCOMMIT();
            CPWAIT1();
        } else {
            CPWAIT0();
        }
        __syncthreads();

        // ---- convert raw(st) -> planes
        {
            const char* rk = smp + K1_RK0 + st * K1_RKS;
            #pragma unroll
            for (int k = 0; k < 32; k++) {
                float v = *(const float*)(rk + k * 896 + t * 4);
                unsigned short h, l;
                split2(v, h, l);
                *(unsigned short*)(smp + K1_PL + t * 80 + k * 2) = h;
                *(unsigned short*)(smp + K1_PL + 17920u + t * 80 + k * 2) = l;
            }
            const char* rq = smp + K1_RQ0 + st * K1_RQS;
            #pragma unroll
            for (int i = 0; i < 16; i++) {
                int idx = t + i * 224;
                int r = idx >> 5, kk = idx & 31;
                float v = *(const float*)(rq + r * 128 + kk * 4);
                unsigned short h, l;
                split2(v, h, l);
                *(unsigned short*)(smp + K1_PL + 35840u + r * 80 + kk * 2) = h;
                *(unsigned short*)(smp + K1_PL + 44800u + r * 80 + kk * 2) = l;
            }
        }
        __syncthreads();

        // ---- MMA on planes
        const u32 ahb = sb + K1_PL;
        const u32 alb = ahb + 17920u;
        const u32 bhb = ahb + 35840u;
        const u32 blb = ahb + 44800u;
        #pragma unroll
        for (int ks = 0; ks < 2; ks++) {
            u32 ah[2][4], al[2][4];
            #pragma unroll
            for (int mt = 0; mt < 2; mt++) {
                u32 arow = w * 32 + mt * 16 + (lane & 15);
                u32 acol = ks * 32 + ((lane >> 4) << 4);
                LDMX4(ah[mt], ahb + arow * 80 + acol);
                LDMX4(al[mt], alb + arow * 80 + acol);
            }
            #pragma unroll
            for (int jj = 0; jj < 7; jj++) {
                u32 brow = jj * 16 + ((lane >> 4) << 3) + (lane & 7);
                u32 bcol = ks * 32 + (((lane >> 3) & 1) << 4);
                u32 bh[4], bl[4];
                LDMX4(bh, bhb + brow * 80 + bcol);
                LDMX4(bl, blb + brow * 80 + bcol);
                #pragma unroll
                for (int mt = 0; mt < 2; mt++) {
                    #pragma unroll
                    for (int hf = 0; hf < 2; hf++) {
                        int j = jj * 2 + hf;
                        MMA16816(acc[mt][j], ah[mt], bh[hf * 2], bh[hf * 2 + 1]);
                        MMA16816(acc[mt][j], ah[mt], bl[hf * 2], bl[hf * 2 + 1]);
                        MMA16816(acc[mt][j], al[mt], bh[hf * 2], bh[hf * 2 + 1]);
                    }
                }
            }
        }
    }
    __syncthreads();   // staging dead; reuse as Csm [224 n][116 f32]

    float* Csm = (float*)smp;
    float* sinv = (float*)(smp + K1_SINV);
    const int g = lane >> 2, tq = lane & 3;
    #pragma unroll
    for (int mt = 0; mt < 2; mt++)
        #pragma unroll
        for (int j = 0; j < 14; j++) {
            int row = w * 32 + mt * 16 + g;
            int col = j * 8 + tq * 2;
            *(float2*)&Csm[row * 116 + col] = make_float2(acc[mt][j][0], acc[mt][j][1]);
            *(float2*)&Csm[(row + 8) * 116 + col] = make_float2(acc[mt][j][2], acc[mt][j][3]);
        }
    __syncthreads();

    // Warp-parallel column softmax: warp w -> a-cols [w*16, w*16+16).
    #pragma unroll 1
    for (int ci = 0; ci < 16; ci++) {
        int c = w * 16 + ci;
        float M = -1e30f;
        #pragma unroll
        for (int r = 0; r < 7; r++) {
            int n = lane + r * 32;
            if (n < NB) M = fmaxf(M, Csm[n * 116 + c]);
        }
        #pragma unroll
        for (int o = 16; o; o >>= 1)
            M = fmaxf(M, __shfl_xor_sync(0xFFFFFFFFu, M, o));
        float S = 0.f;
        #pragma unroll
        for (int r = 0; r < 7; r++) {
            int n = lane + r * 32;
            if (n < NB) {
                float e = __expf(SMOOTH_F * (Csm[n * 116 + c] - M));
                Csm[n * 116 + c] = e;
                S += e;
            }
        }
        #pragma unroll
        for (int o = 16; o; o >>= 1)
            S += __shfl_xor_sync(0xFFFFFFFFu, S, o);
        if (lane == 0)
            sinv[c] = (a0 + c < NA) ? (1.f / S) : 0.f;
    }
    __syncthreads();

    // Write fp16 attn plane (coalesced rows; zero rows for n >= 196).
    if (lane < 28) {
        float4 s4 = *(float4*)&sinv[lane * 4];
        for (int r = w; r < NP; r += 7) {
            uint2 hh = make_uint2(0u, 0u);
            if (r < NB) {
                float4 p = *(float4*)&Csm[r * 116 + lane * 4];
                unsigned short h0 = __half_as_ushort(__float2half_rn(p.x * s4.x));
                unsigned short h1 = __half_as_ushort(__float2half_rn(p.y * s4.y));
                unsigned short h2 = __half_as_ushort(__float2half_rn(p.z * s4.z));
                unsigned short h3 = __half_as_ushort(__float2half_rn(p.w * s4.w));
                hh = make_uint2((u32)h0 | ((u32)h1 << 16), (u32)h2 | ((u32)h3 << 16));
            }
            size_t off = (size_t)(b * NP + r) * NP + a0 + lane * 4;
            *(uint2*)(g_ah + off) = hh;
        }
    }
}

// ============================================================================
// K2: out = gamma + V_a @ attn + V_b  (fp16 single-plane V_a x fp16 attn:
// 1 MMA product — half the tensor work of round 14's 2-plane split).
// Block: 128 threads = 4 M-warps, tile m128 x n112; warp tile m32 x n112.
// ============================================================================
#define K2_ASTG 10240u                // per stage: 1 plane x (128 x 80B)
#define K2_B0   20480u                // B stages: [112 n][32 k] fp16, 80B stride
#define K2_BSTAGE 8960u               // single plane per stage
#define K2_SMEM 38400u

__global__ void __launch_bounds__(128, 3) xattn_k2(
    const float* __restrict__ VA,   // [B, DIM, NA]
    const float* __restrict__ VB,   // [B, DIM, NB]
    const float* __restrict__ G,
    float* __restrict__ O)          // [B, DIM, NB]
{
    extern __shared__ char smp[];
    const u32 sb = smem_u32(smp);
    const int t = threadIdx.x, lane = t & 31, w = t >> 5;
    const int m0  = (blockIdx.x >> 1) * 128;
    const int nb0 = (blockIdx.x & 1) * 112;
    const int b   = blockIdx.y;

    const float* va = VA + ((size_t)b * DIM + m0) * NA;
    const char* ghp = (const char*)g_ah;

    // ---- prologue: B chunk 0 via cp.async, A chunk 0 fp16-stored to stage 0
    {
        #pragma unroll
        for (int i = 0; i < 4; i++) {
            int idx = t + i * 128;
            if (idx < 448) {
                int n = idx >> 2, c = idx & 3;
                u32 dst = sb + K2_B0 + n * 80 + c * 16;
                const char* src = ghp + ((size_t)(b * NP + nb0 + n) * NP + c * 8) * 2;
                CPASYNC16(dst, src);
            }
        }
        CPCOMMIT();
        #pragma unroll
        for (int i = 0; i < 8; i++) {
            int idx = t + i * 128;
            int row = idx >> 3, q4 = idx & 7;
            int col = q4 * 4;
            float4 v = make_float4(0.f, 0.f, 0.f, 0.f);
            if (col < NA) v = *(const float4*)(va + (size_t)row * NA + col);
            unsigned short h0 = __half_as_ushort(__float2half_rn(v.x));
            unsigned short h1 = __half_as_ushort(__float2half_rn(v.y));
            unsigned short h2 = __half_as_ushort(__float2half_rn(v.z));
            unsigned short h3 = __half_as_ushort(__float2half_rn(v.w));
            *(uint2*)(smp + row * 80 + col * 2) =
                make_uint2((u32)h0 | ((u32)h1 << 16), (u32)h2 | ((u32)h3 << 16));
        }
    }

    float acc[2][14][4];
    #pragma unroll
    for (int mt = 0; mt < 2; mt++)
        #pragma unroll
        for (int j = 0; j < 14; j++)
            #pragma unroll
            for (int q = 0; q < 4; q++) acc[mt][j][q] = 0.f;

    #pragma unroll 1
    for (int kc = 0; kc < 7; kc++) {
        if (kc < 6) {   // prefetch next B chunk + fill next A stage
            const int nk = kc + 1, st = nk & 1;
            #pragma unroll
            for (int i = 0; i < 4; i++) {
                int idx = t + i * 128;
                if (idx < 448) {
                    int n = idx >> 2, c = idx & 3;
                    u32 dst = sb + K2_B0 + st * K2_BSTAGE + n * 80 + c * 16;
                    const char* src = ghp +
                        ((size_t)(b * NP + nb0 + n) * NP + nk * 32 + c * 8) * 2;
                    CPASYNC16(dst, src);
                }
            }
            #pragma unroll
            for (int i = 0; i < 8; i++) {
                int idx = t + i * 128;
                int row = idx >> 3, q4 = idx & 7;
                int col = q4 * 4;
                int ac = nk * 32 + col;
                float4 v = make_float4(0.f, 0.f, 0.f, 0.f);
                if (ac < NA) v = *(const float4*)(va + (size_t)row * NA + ac);
                unsigned short h0 = __half_as_ushort(__float2half_rn(v.x));
                unsigned short h1 = __half_as_ushort(__float2half_rn(v.y));
                unsigned short h2 = __half_as_ushort(__float2half_rn(v.z));
                unsigned short h3 = __half_as_ushort(__float2half_rn(v.w));
                *(uint2*)(smp + st * K2_ASTG + row * 80 + col * 2) =
                    make_uint2((u32)h0 | ((u32)h1 << 16), (u32)h2 | ((u32)h3 << 16));
            }
        }
        CPCOMMIT();
        CPWAIT1();
        __syncthreads();

        const u32 ahb = sb + (kc & 1) * K2_ASTG;
        const u32 bhb = sb + K2_B0 + (kc & 1) * K2_BSTAGE;

        #pragma unroll
        for (int ks = 0; ks < 2; ks++) {
            u32 ah[2][4];
            #pragma unroll
            for (int mt = 0; mt < 2; mt++) {
                u32 arow = w * 32 + mt * 16 + (lane & 15);
                u32 acol = ks * 32 + ((lane >> 4) << 4);
                LDMX4(ah[mt], ahb + arow * 80 + acol);
            }
            #pragma unroll
            for (int jj = 0; jj < 7; jj++) {
                u32 brow = jj * 16 + ((lane >> 4) << 3) + (lane & 7);
                u32 bcol = ks * 32 + (((lane >> 3) & 1) << 4);
                u32 bh[4];
                LDMX4(bh, bhb + brow * 80 + bcol);
                #pragma unroll
                for (int mt = 0; mt < 2; mt++) {
                    #pragma unroll
                    for (int hf = 0; hf < 2; hf++) {
                        int j = jj * 2 + hf;
                        MMAF16816(acc[mt][j], ah[mt], bh[hf * 2], bh[hf * 2 + 1]);
                    }
                }
            }
        }
        __syncthreads();
    }

    // Epilogue: out = gamma + acc + V_b (guarded float2 stores)
    const float gam = G[0];
    const int g = lane >> 2, tq = lane & 3;
    #pragma unroll
    for (int mt = 0; mt < 2; mt++)
        #pragma unroll
        for (int j = 0; j < 14; j++) {
            int n = nb0 + j * 8 + tq * 2;
            if (n < NB) {
                int row = m0 + w * 32 + mt * 16 + g;
                size_t o0 = ((size_t)(b * DIM + row)) * NB + n;
                size_t o1 = o0 + (size_t)8 * NB;
                float2 v0 = *(const float2*)(VB + o0);
                float2 v1 = *(const float2*)(VB + o1);
                *(float2*)(O + o0) = make_float2(gam + acc[mt][j][0] + v0.x,
                                                 gam + acc[mt][j][1] + v0.y);
                *(float2*)(O + o1) = make_float2(gam + acc[mt][j][2] + v1.x,
                                                 gam + acc[mt][j][3] + v1.y);
            }
        }
}

// ============================================================================
extern "C" void kernel_launch(void* const* d_in, const int* in_sizes, int n_in,
                              void* d_out, int out_size)
{
    const float* query_a = (const float*)d_in[0];
    const float* value_a = (const float*)d_in[1];
    const float* key_b   = (const float*)d_in[2];
    const float* value_b = (const float*)d_in[3];
    const float* gamma   = (const float*)d_in[4];
    float* out = (float*)d_out;

    cudaFuncSetAttribute(xattn_k1, cudaFuncAttributeMaxDynamicSharedMemorySize, K1_SMEM);
    cudaFuncSetAttribute(xattn_k2, cudaFuncAttributeMaxDynamicSharedMemorySize, K2_SMEM);

    xattn_k1<<<dim3(2, BATCH), 224, K1_SMEM>>>(query_a, key_b);
    xattn_k2<<<dim3(16, BATCH), 128, K2_SMEM>>>(value_a, value_b, gamma, out);
}